// round 4
// baseline (speedup 1.0000x reference)
#include <cuda_runtime.h>
#include <cstdint>
#include <math_constants.h>

// Problem constants (fixed by the reference: M=4 molecules, N=2048 atoms)
#define NATOMS 2048
#define NMOL   4
#define NPAIR  2096128                          // N*(N-1)/2
#define MP     ((size_t)NMOL * (size_t)NPAIR)   // 8,384,512

// Output layout (flattened concat of the reference tuple, float32):
//   [0,    2*MP) : atom_index12 ([2, M*P] row-major, as float)
//   [2*MP, 5*MP) : shift_values ([M*P, 3], all zeros)
//   [5*MP, 6*MP) : mask         ([M*P], 1.0/0.0)

__device__ __forceinline__ int row_offset(int i) {
    // offset of row i in triu_indices(N, k=1): i*(2N-1-i)/2
    return (i * (2 * NATOMS - 1 - i)) >> 1;
}

// One block = one 32(i) x 256(j) tile of the upper triangle, one molecule.
__global__ __launch_bounds__(256)
void fp_tiled(const int*   __restrict__ species,
              const float* __restrict__ coords,
              float*       __restrict__ out)
{
    const int a  = blockIdx.x;            // i-tile: i in [32a, 32a+32)
    const int b  = blockIdx.y;            // j-tile: j in [256b, 256b+256)
    const int m  = blockIdx.z;            // molecule
    const int i0 = a * 32;
    const int j0 = b * 256;
    if (i0 >= j0 + 255) return;           // tile entirely on/below diagonal

    __shared__ float4 cj[256];
    __shared__ float4 ci[32];

    const int t = threadIdx.x;
    const float* __restrict__ cb = coords  + (size_t)m * NATOMS * 3;
    const int*   __restrict__ sb = species + m * NATOMS;

    // Load tile atoms once; fold species==-1 -> NaN (NaN<=cut2 is false,
    // exactly matching the reference's masked_fill + <= semantics).
    {
        const int j = j0 + t;
        float x = cb[3 * j], y = cb[3 * j + 1], z = cb[3 * j + 2];
        if (sb[j] == -1) { x = CUDART_NAN_F; y = CUDART_NAN_F; z = CUDART_NAN_F; }
        cj[t] = make_float4(x, y, z, 0.f);
        if (t < 32) {
            const int i = i0 + t;
            float xi = cb[3 * i], yi = cb[3 * i + 1], zi = cb[3 * i + 2];
            if (sb[i] == -1) { xi = CUDART_NAN_F; yi = CUDART_NAN_F; zi = CUDART_NAN_F; }
            ci[t] = make_float4(xi, yi, zi, 0.f);
        }
    }
    __syncthreads();

    const float  cut2 = 5.2f * 5.2f;            // fp32, matches jnp
    const float  foff = (float)(m * NATOMS);
    const size_t qm   = (size_t)m * NPAIR;

    #pragma unroll 4
    for (int r = 0; r < 32; ++r) {
        const int i   = i0 + r;
        const int jlo = (i + 1 > j0) ? i + 1 : j0;     // enforce j > i
        const int n   = j0 + 256 - jlo;                // pairs in this row-tile
        if (n <= 0) continue;                          // only near row 2047 / diag
        const size_t q0 = qm + (size_t)(row_offset(i) + jlo - i - 1);

        const float4 c1 = ci[r];                       // smem broadcast
        if (t < n) {
            const float4 c2 = cj[jlo - j0 + t];        // stride-1, conflict-free
            const float dx = c1.x - c2.x;
            const float dy = c1.y - c2.y;
            const float dz = c1.z - c2.z;
            // exact fp32, no FMA contraction, jnp reduction order ((x^2+y^2)+z^2)
            const float d2 = __fadd_rn(__fadd_rn(__fmul_rn(dx, dx),
                                                 __fmul_rn(dy, dy)),
                                       __fmul_rn(dz, dz));
            out[q0 + t]          = (float)i + foff;            // idx row 0
            out[MP + q0 + t]     = (float)(jlo + t) + foff;    // idx row 1
            out[5 * MP + q0 + t] = (d2 <= cut2) ? 1.f : 0.f;   // mask
        }

        // shift_values: 3n contiguous zero floats, coalesced stride-256 fill
        float* oz = out + 2 * MP + 3 * q0;
        const int zn = 3 * n;
        for (int u = t; u < zn; u += 256) oz[u] = 0.f;
    }
}

extern "C" void kernel_launch(void* const* d_in, const int* in_sizes, int n_in,
                              void* d_out, int out_size)
{
    const int*   species = (const int*)  d_in[0];
    const float* coords  = (const float*)d_in[1];
    float*       out     = (float*)d_out;

    dim3 grid(64, 8, NMOL);     // (i-tiles, j-tiles, molecules); invalid tiles exit
    fp_tiled<<<grid, 256>>>(species, coords, out);
}

// round 5
// speedup vs baseline: 1.9211x; 1.9211x over previous
#include <cuda_runtime.h>
#include <cstdint>
#include <math_constants.h>

// Problem constants (fixed by the reference: M=4 molecules, N=2048 atoms)
#define NATOMS  2048
#define NMOL    4
#define NPAIRU  2096128u                        // N*(N-1)/2
#define MPU     (4u * NPAIRU)                   // 8,384,512  (< 2^31 even *6)

// Output layout (flattened concat of the reference tuple, float32):
//   [0,     2*MP) : atom_index12 ([2, M*P] row-major, as float)
//   [2*MP,  5*MP) : shift_values ([M*P, 3], all zeros)
//   [5*MP,  6*MP) : mask         ([M*P], 1.0/0.0)

// Scratch: coords packed as float4 per atom, NaN-filled where species == -1.
__device__ float4 g_c4[NMOL * NATOMS];

__device__ __forceinline__ int row_offset(int i) {
    // offset of row i in triu_indices(N, k=1): i*(2N-1-i)/2
    return (i * (2 * NATOMS - 1 - i)) >> 1;
}

__global__ void prep_kernel(const int*   __restrict__ species,
                            const float* __restrict__ coords)
{
    const int a = blockIdx.x * blockDim.x + threadIdx.x;   // 0 .. NMOL*NATOMS-1
    float x = coords[3 * a + 0];
    float y = coords[3 * a + 1];
    float z = coords[3 * a + 2];
    if (species[a] == -1) { x = CUDART_NAN_F; y = CUDART_NAN_F; z = CUDART_NAN_F; }
    g_c4[a] = make_float4(x, y, z, 0.0f);
}

__global__ __launch_bounds__(256)
void fullpairwise_kernel(float* __restrict__ out)
{
    const int      m   = blockIdx.y;
    const unsigned tid = threadIdx.x;
    const unsigned p0  = blockIdx.x * 1024u + tid;   // pair id for k=0
    // grid.x = NPAIR/1024 = 2047 exactly -> no bounds checks

    const float4* __restrict__ cm = g_c4 + m * NATOMS;
    const float    cut2 = 5.2f * 5.2f;               // fp32, matches jnp
    const float    foff = (float)(m * NATOMS);
    const unsigned qm   = (unsigned)m * NPAIRU;      // molecule offset (32-bit)

    // ---- zeros region: flat fill, coalesced STG.128, streaming (evict-first) ----
    {
        const unsigned zoff = 2u * MPU + 3u * (qm + blockIdx.x * 1024u);
        float4* zp = reinterpret_cast<float4*>(out + zoff);   // 768 float4/block
        const float4 z4 = make_float4(0.f, 0.f, 0.f, 0.f);
        __stcs(zp + tid,        z4);
        __stcs(zp + tid + 256u, z4);
        __stcs(zp + tid + 512u, z4);
    }

    // ---- pair work: lane-consecutive p => coalesced loads & scalar stores ----
    #pragma unroll
    for (int k = 0; k < 4; ++k) {
        const unsigned p  = p0 + (unsigned)k * 256u;
        const int      pi = (int)p;

        // invert triangular index: disc = 4095^2 - 8p < 2^24, exact in fp32;
        // sqrtf estimate fixed up to exactness by the +/-1 loops (rarely taken).
        const int disc = 16769025 - 8 * pi;
        int i = (int)((4095.0f - sqrtf((float)disc)) * 0.5f);
        if (i < 0) i = 0;
        while (row_offset(i + 1) <= pi) ++i;
        while (row_offset(i) > pi)      --i;
        const int j = i + 1 + (pi - row_offset(i));

        const float4 ci = __ldg(&cm[i]);   // warp-uniform-ish broadcast
        const float4 cj = __ldg(&cm[j]);   // lane-consecutive -> coalesced

        const float dx = ci.x - cj.x;
        const float dy = ci.y - cj.y;
        const float dz = ci.z - cj.z;
        // exact fp32, no FMA contraction, jnp reduction order ((x^2+y^2)+z^2);
        // NaN (padded atoms) compares false, matching the reference mask.
        const float d2 = __fadd_rn(__fadd_rn(__fmul_rn(dx, dx),
                                             __fmul_rn(dy, dy)),
                                   __fmul_rn(dz, dz));
        const float ok = (d2 <= cut2) ? 1.0f : 0.0f;

        const unsigned q = qm + p;                       // 32-bit index math
        __stcs(out + q,            (float)i + foff);     // atom_index12 row 0
        __stcs(out + MPU + q,      (float)j + foff);     // atom_index12 row 1
        __stcs(out + 5u * MPU + q, ok);                  // mask
    }
}

extern "C" void kernel_launch(void* const* d_in, const int* in_sizes, int n_in,
                              void* d_out, int out_size)
{
    const int*   species = (const int*)  d_in[0];
    const float* coords  = (const float*)d_in[1];
    float*       out     = (float*)d_out;

    prep_kernel<<<(NMOL * NATOMS) / 256, 256>>>(species, coords);

    dim3 grid(NPAIRU / 1024u, NMOL);   // (2047, 4), exact coverage
    fullpairwise_kernel<<<grid, 256>>>(out);
}